// round 8
// baseline (speedup 1.0000x reference)
#include <cuda_runtime.h>

#define KTOT   1000000
#define NCOLS  70400
#define SENT   -9999999.0f

typedef unsigned long long u64;

// Port split: W3/W4/b3/b4 on the constant port (LDC), W1/W2 in shared (LDS).
__constant__ ulonglong2 cW3v[324];   // W3: 1296 floats, row = 9 ulonglong2
__constant__ float      cW4f[36];
__constant__ float      cb3f[36], cb4f[1];

static __device__ __forceinline__ u64 pack2(float lo, float hi) {
    u64 r; asm("mov.b64 %0,{%1,%2};" : "=l"(r) : "f"(lo), "f"(hi)); return r;
}
static __device__ __forceinline__ void unpack2(u64 v, float& lo, float& hi) {
    asm("mov.b64 {%0,%1},%2;" : "=f"(lo), "=f"(hi) : "l"(v));
}
static __device__ __forceinline__ u64 fma2(u64 a, u64 b, u64 c) {
    u64 d; asm("fma.rn.f32x2 %0,%1,%2,%3;" : "=l"(d) : "l"(a), "l"(b), "l"(c)); return d;
}
// horizontal add of the two f32 lanes (bias pre-folded into lane 0)
static __device__ __forceinline__ float hadd(u64 v) {
    float lo, hi; unpack2(v, lo, hi);
    return lo + hi;
}
// float atomic max via sign-split integer atomics (no return -> REDG)
static __device__ __forceinline__ void atomicMaxF(float* a, float v) {
    if (v >= 0.0f) atomicMax((int*)a, __float_as_int(v));
    else           atomicMin((unsigned int*)a, __float_as_uint(v));
}

__global__ void init_out_kernel(float* out, int n) {
    int i = blockIdx.x * blockDim.x + threadIdx.x;
    if (i < n) out[i] = (i < NCOLS) ? SENT : 1.0f;   // trailing element(s) = flag
}

__global__ __launch_bounds__(128, 4) void mlp_scatter_kernel(
    const float* __restrict__ x,        // (4, K) row-major
    const int* __restrict__ tix,        // (K, 2) int32, col index at [2k+1]
    const float* __restrict__ W1, const float* __restrict__ b1,
    const float* __restrict__ W2, const float* __restrict__ b2,
    float* __restrict__ out)
{
    // W1: 18 rows x 4 w = 1 ulonglong2/row ; W2: 36 rows x 18 w = 4 ulonglong2 + u64 tail
    __shared__ ulonglong2 sW1[18];
    __shared__ ulonglong2 sW2[144];
    __shared__ u64        sW2t[36];
    __shared__ u64 sb1[18], sb2[36];

    const int t = threadIdx.x;
    for (int i = t; i < 18;  i += 128) sW1[i] = ((const ulonglong2*)W1)[i];
    for (int i = t; i < 18;  i += 128) sb1[i] = pack2(b1[i], 0.0f);
    for (int i = t; i < 144; i += 128) {
        int row = i >> 2, q = i & 3;
        sW2[i] = make_ulonglong2(((const u64*)W2)[row * 9 + 2 * q],
                                 ((const u64*)W2)[row * 9 + 2 * q + 1]);
    }
    for (int i = t; i < 36;  i += 128) sW2t[i] = ((const u64*)W2)[i * 9 + 8];
    for (int i = t; i < 36;  i += 128) sb2[i] = pack2(b2[i], 0.0f);
    __syncthreads();

    const unsigned k0 = 2u * (blockIdx.x * 128u + (unsigned)t);
    if (k0 >= KTOT) return;

    // Two adjacent columns; k-pack each column's 4 input features into 2 u64.
    float2 r0 = *reinterpret_cast<const float2*>(x + 0 * (size_t)KTOT + k0);
    float2 r1 = *reinterpret_cast<const float2*>(x + 1 * (size_t)KTOT + k0);
    float2 r2 = *reinterpret_cast<const float2*>(x + 2 * (size_t)KTOT + k0);
    float2 r3 = *reinterpret_cast<const float2*>(x + 3 * (size_t)KTOT + k0);
    u64 xv00 = pack2(r0.x, r1.x), xv01 = pack2(r2.x, r3.x);
    u64 xv10 = pack2(r0.y, r1.y), xv11 = pack2(r2.y, r3.y);

    // ---- Layer 1: 4 -> 18 (shared weights), outputs packed: h1[c][j/2] ----
    u64 h1[2][9];
    #pragma unroll
    for (int j = 0; j < 18; j += 2) {
        float ho[2][2];
        #pragma unroll
        for (int s = 0; s < 2; s++) {
            const int jj = j + s;
            ulonglong2 w = sW1[jj];
            u64 bb = sb1[jj];
            u64 a0 = fma2(w.x, xv00, bb);
            u64 a1 = fma2(w.x, xv10, bb);
            a0 = fma2(w.y, xv01, a0);
            a1 = fma2(w.y, xv11, a1);
            ho[s][0] = fmaxf(hadd(a0), 0.0f);
            ho[s][1] = fmaxf(hadd(a1), 0.0f);
        }
        h1[0][j / 2] = pack2(ho[0][0], ho[1][0]);
        h1[1][j / 2] = pack2(ho[0][1], ho[1][1]);
    }

    // ---- Layer 2: 18 -> 36 (shared weights), outputs packed: h2[c][j/2] ----
    u64 h2[2][18];
    #pragma unroll 2
    for (int j = 0; j < 36; j += 2) {
        float ho[2][2];
        #pragma unroll
        for (int s = 0; s < 2; s++) {
            const int jj = j + s;
            u64 a0 = sb2[jj], a1 = sb2[jj];
            #pragma unroll
            for (int q = 0; q < 4; q++) {
                ulonglong2 w = sW2[jj * 4 + q];
                a0 = fma2(w.x, h1[0][2 * q], a0);
                a1 = fma2(w.x, h1[1][2 * q], a1);
                a0 = fma2(w.y, h1[0][2 * q + 1], a0);
                a1 = fma2(w.y, h1[1][2 * q + 1], a1);
            }
            u64 wt = sW2t[jj];
            a0 = fma2(wt, h1[0][8], a0);
            a1 = fma2(wt, h1[1][8], a1);
            ho[s][0] = fmaxf(hadd(a0), 0.0f);
            ho[s][1] = fmaxf(hadd(a1), 0.0f);
        }
        h2[0][j / 2] = pack2(ho[0][0], ho[1][0]);
        h2[1][j / 2] = pack2(ho[0][1], ho[1][1]);
    }

    // ---- Layers 3+4 fused (constant-port weights): 36 -> 36 -> 1 ----
    // One row at a time; v accumulated with scalar FFMA (no output pairing).
    float v0 = cb4f[0], v1 = cb4f[0];
    #pragma unroll 3
    for (int j = 0; j < 36; j++) {
        u64 bb = pack2(cb3f[j], 0.0f);
        u64 a0 = bb, a1 = bb;
        #pragma unroll
        for (int q = 0; q < 9; q++) {
            ulonglong2 w = cW3v[j * 9 + q];
            a0 = fma2(w.x, h2[0][2 * q], a0);
            a1 = fma2(w.x, h2[1][2 * q], a1);
            a0 = fma2(w.y, h2[0][2 * q + 1], a0);
            a1 = fma2(w.y, h2[1][2 * q + 1], a1);
        }
        float w4 = cW4f[j];
        v0 = fmaf(w4, fmaxf(hadd(a0), 0.0f), v0);
        v1 = fmaf(w4, fmaxf(hadd(a1), 0.0f), v1);
    }

    // (K,2) int32: one int4 covers both pairs; columns at .y/.w
    const int4 p = *reinterpret_cast<const int4*>(tix + 2 * (size_t)k0);
    if ((unsigned)p.y < NCOLS) atomicMaxF(out + p.y, v0);
    if ((unsigned)p.w < NCOLS) atomicMaxF(out + p.w, v1);
}

extern "C" void kernel_launch(void* const* d_in, const int* in_sizes, int n_in,
                              void* d_out, int out_size) {
    const float* x   = (const float*)d_in[0];
    const int*   tix = (const int*)d_in[1];
    const float* W1 = (const float*)d_in[2];
    const float* b1 = (const float*)d_in[3];
    const float* W2 = (const float*)d_in[4];
    const float* b2 = (const float*)d_in[5];
    float* out = (float*)d_out;

    // Stage the big layer into constant memory (async D2D memcpy nodes).
    cudaMemcpyToSymbolAsync(cW3v, d_in[6], 1296 * 4, 0, cudaMemcpyDeviceToDevice);
    cudaMemcpyToSymbolAsync(cb3f, d_in[7],   36 * 4, 0, cudaMemcpyDeviceToDevice);
    cudaMemcpyToSymbolAsync(cW4f, d_in[8],   36 * 4, 0, cudaMemcpyDeviceToDevice);
    cudaMemcpyToSymbolAsync(cb4f, d_in[9],    1 * 4, 0, cudaMemcpyDeviceToDevice);

    init_out_kernel<<<(out_size + 255) / 256, 256>>>(out, out_size);

    const int nthreads = KTOT / 2;                 // 2 columns per thread
    mlp_scatter_kernel<<<(nthreads + 127) / 128, 128>>>(
        x, tix, W1, b1, W2, b2, out);
}

// round 9
// speedup vs baseline: 1.1467x; 1.1467x over previous
#include <cuda_runtime.h>

#define KTOT   1000000
#define NCOLS  70400
#define SENT   -9999999.0f

typedef unsigned long long u64;

// Port split inside layer 3: W3 rows 0..17 via shared (LDS), rows 18..35 via
// constant (LDC). Each inner iteration touches both ports concurrently.
__constant__ ulonglong2 cW3hi[162];  // W3 rows 18..35 (18 rows x 9 ulonglong2)
__constant__ float      cW4f[36];
__constant__ float      cb3f[36], cb4f[1];

static __device__ __forceinline__ u64 pack2(float lo, float hi) {
    u64 r; asm("mov.b64 %0,{%1,%2};" : "=l"(r) : "f"(lo), "f"(hi)); return r;
}
static __device__ __forceinline__ void unpack2(u64 v, float& lo, float& hi) {
    asm("mov.b64 {%0,%1},%2;" : "=f"(lo), "=f"(hi) : "l"(v));
}
static __device__ __forceinline__ u64 fma2(u64 a, u64 b, u64 c) {
    u64 d; asm("fma.rn.f32x2 %0,%1,%2,%3;" : "=l"(d) : "l"(a), "l"(b), "l"(c)); return d;
}
// horizontal add of the two f32 lanes (bias pre-folded into lane 0)
static __device__ __forceinline__ float hadd(u64 v) {
    float lo, hi; unpack2(v, lo, hi);
    return lo + hi;
}
// float atomic max via sign-split integer atomics (no return -> REDG)
static __device__ __forceinline__ void atomicMaxF(float* a, float v) {
    if (v >= 0.0f) atomicMax((int*)a, __float_as_int(v));
    else           atomicMin((unsigned int*)a, __float_as_uint(v));
}

__global__ void init_out_kernel(float* out, int n) {
    int i = blockIdx.x * blockDim.x + threadIdx.x;
    if (i < n) out[i] = (i < NCOLS) ? SENT : 1.0f;   // trailing element(s) = flag
}

__global__ __launch_bounds__(128, 3) void mlp_scatter_kernel(
    const float* __restrict__ x,        // (4, K) row-major
    const int* __restrict__ tix,        // (K, 2) int32, col index at [2k+1]
    const float* __restrict__ W1, const float* __restrict__ b1,
    const float* __restrict__ W2, const float* __restrict__ b2,
    const float* __restrict__ W3lo,     // = W3 (rows 0..17 used)
    float* __restrict__ out)
{
    __shared__ ulonglong2 sW1[18];      // W1: 18 rows x 4 w
    __shared__ ulonglong2 sW2[144];     // W2: 36 rows x (4 x ulonglong2)
    __shared__ u64        sW2t[36];     // W2 row tails
    __shared__ ulonglong2 sW3lo[162];   // W3 rows 0..17 (9 ulonglong2/row)
    __shared__ u64 sb1[18], sb2[36];

    const int t = threadIdx.x;
    for (int i = t; i < 18;  i += 128) sW1[i] = ((const ulonglong2*)W1)[i];
    for (int i = t; i < 18;  i += 128) sb1[i] = pack2(b1[i], 0.0f);
    for (int i = t; i < 144; i += 128) {
        int row = i >> 2, q = i & 3;
        sW2[i] = make_ulonglong2(((const u64*)W2)[row * 9 + 2 * q],
                                 ((const u64*)W2)[row * 9 + 2 * q + 1]);
    }
    for (int i = t; i < 36;  i += 128) sW2t[i] = ((const u64*)W2)[i * 9 + 8];
    for (int i = t; i < 36;  i += 128) sb2[i] = pack2(b2[i], 0.0f);
    for (int i = t; i < 162; i += 128) sW3lo[i] = ((const ulonglong2*)W3lo)[i];
    __syncthreads();

    const unsigned k0 = 2u * (blockIdx.x * 128u + (unsigned)t);
    if (k0 >= KTOT) return;

    // Two adjacent columns; k-pack each column's 4 input features into 2 u64.
    float2 r0 = *reinterpret_cast<const float2*>(x + 0 * (size_t)KTOT + k0);
    float2 r1 = *reinterpret_cast<const float2*>(x + 1 * (size_t)KTOT + k0);
    float2 r2 = *reinterpret_cast<const float2*>(x + 2 * (size_t)KTOT + k0);
    float2 r3 = *reinterpret_cast<const float2*>(x + 3 * (size_t)KTOT + k0);
    u64 xv00 = pack2(r0.x, r1.x), xv01 = pack2(r2.x, r3.x);
    u64 xv10 = pack2(r0.y, r1.y), xv11 = pack2(r2.y, r3.y);

    // ---- Layer 1: 4 -> 18 (shared weights), outputs packed: h1[c][j/2] ----
    u64 h1[2][9];
    #pragma unroll
    for (int j = 0; j < 18; j += 2) {
        float ho[2][2];
        #pragma unroll
        for (int s = 0; s < 2; s++) {
            const int jj = j + s;
            ulonglong2 w = sW1[jj];
            u64 bb = sb1[jj];
            u64 a0 = fma2(w.x, xv00, bb);
            u64 a1 = fma2(w.x, xv10, bb);
            a0 = fma2(w.y, xv01, a0);
            a1 = fma2(w.y, xv11, a1);
            ho[s][0] = fmaxf(hadd(a0), 0.0f);
            ho[s][1] = fmaxf(hadd(a1), 0.0f);
        }
        h1[0][j / 2] = pack2(ho[0][0], ho[1][0]);
        h1[1][j / 2] = pack2(ho[0][1], ho[1][1]);
    }

    // ---- Layer 2: 18 -> 36 (shared weights), outputs packed: h2[c][j/2] ----
    u64 h2[2][18];
    #pragma unroll 4
    for (int j = 0; j < 36; j += 2) {
        float ho[2][2];
        #pragma unroll
        for (int s = 0; s < 2; s++) {
            const int jj = j + s;
            u64 a0 = sb2[jj], a1 = sb2[jj];
            #pragma unroll
            for (int q = 0; q < 4; q++) {
                ulonglong2 w = sW2[jj * 4 + q];
                a0 = fma2(w.x, h1[0][2 * q], a0);
                a1 = fma2(w.x, h1[1][2 * q], a1);
                a0 = fma2(w.y, h1[0][2 * q + 1], a0);
                a1 = fma2(w.y, h1[1][2 * q + 1], a1);
            }
            u64 wt = sW2t[jj];
            a0 = fma2(wt, h1[0][8], a0);
            a1 = fma2(wt, h1[1][8], a1);
            ho[s][0] = fmaxf(hadd(a0), 0.0f);
            ho[s][1] = fmaxf(hadd(a1), 0.0f);
        }
        h2[0][j / 2] = pack2(ho[0][0], ho[1][0]);
        h2[1][j / 2] = pack2(ho[0][1], ho[1][1]);
    }

    // ---- Layers 3+4 fused: 36 -> 36 -> 1 ----
    // Row pair (jj, jj+18): row jj weights from SMEM (LDS port), row jj+18
    // from constant (LDC port). 4 accumulator chains (2 rows x 2 cols).
    float v0 = cb4f[0], v1 = cb4f[0];
    #pragma unroll 3
    for (int jj = 0; jj < 18; jj++) {
        u64 bbA = pack2(cb3f[jj], 0.0f);
        u64 bbB = pack2(cb3f[jj + 18], 0.0f);
        u64 a0 = bbA, a1 = bbA;          // row jj   (shared)
        u64 c0 = bbB, c1 = bbB;          // row jj+18 (constant)
        #pragma unroll
        for (int q = 0; q < 9; q++) {
            ulonglong2 wA = sW3lo[jj * 9 + q];
            ulonglong2 wB = cW3hi[jj * 9 + q];
            a0 = fma2(wA.x, h2[0][2 * q], a0);
            a1 = fma2(wA.x, h2[1][2 * q], a1);
            c0 = fma2(wB.x, h2[0][2 * q], c0);
            c1 = fma2(wB.x, h2[1][2 * q], c1);
            a0 = fma2(wA.y, h2[0][2 * q + 1], a0);
            a1 = fma2(wA.y, h2[1][2 * q + 1], a1);
            c0 = fma2(wB.y, h2[0][2 * q + 1], c0);
            c1 = fma2(wB.y, h2[1][2 * q + 1], c1);
        }
        float w4A = cW4f[jj], w4B = cW4f[jj + 18];
        v0 = fmaf(w4A, fmaxf(hadd(a0), 0.0f), v0);
        v1 = fmaf(w4A, fmaxf(hadd(a1), 0.0f), v1);
        v0 = fmaf(w4B, fmaxf(hadd(c0), 0.0f), v0);
        v1 = fmaf(w4B, fmaxf(hadd(c1), 0.0f), v1);
    }

    // (K,2) int32: one int4 covers both pairs; columns at .y/.w
    const int4 p = *reinterpret_cast<const int4*>(tix + 2 * (size_t)k0);
    if ((unsigned)p.y < NCOLS) atomicMaxF(out + p.y, v0);
    if ((unsigned)p.w < NCOLS) atomicMaxF(out + p.w, v1);
}

extern "C" void kernel_launch(void* const* d_in, const int* in_sizes, int n_in,
                              void* d_out, int out_size) {
    const float* x   = (const float*)d_in[0];
    const int*   tix = (const int*)d_in[1];
    const float* W1 = (const float*)d_in[2];
    const float* b1 = (const float*)d_in[3];
    const float* W2 = (const float*)d_in[4];
    const float* b2 = (const float*)d_in[5];
    const float* W3 = (const float*)d_in[6];
    float* out = (float*)d_out;

    // Upper half of W3 (rows 18..35) + b3/W4/b4 onto the constant port.
    cudaMemcpyToSymbolAsync(cW3hi, (const char*)d_in[6] + 648 * 4, 648 * 4, 0,
                            cudaMemcpyDeviceToDevice);
    cudaMemcpyToSymbolAsync(cb3f, d_in[7], 36 * 4, 0, cudaMemcpyDeviceToDevice);
    cudaMemcpyToSymbolAsync(cW4f, d_in[8], 36 * 4, 0, cudaMemcpyDeviceToDevice);
    cudaMemcpyToSymbolAsync(cb4f, d_in[9],  1 * 4, 0, cudaMemcpyDeviceToDevice);

    init_out_kernel<<<(out_size + 255) / 256, 256>>>(out, out_size);

    const int nthreads = KTOT / 2;                 // 2 columns per thread
    mlp_scatter_kernel<<<(nthreads + 127) / 128, 128>>>(
        x, tix, W1, b1, W2, b2, W3, out);
}

// round 10
// speedup vs baseline: 1.2860x; 1.1215x over previous
#include <cuda_runtime.h>

#define KTOT   1000000
#define NCOLS  70400
#define SENT   -9999999.0f

typedef unsigned long long u64;

// W3/W4/b3/b4 on the constant port; W1/W2 in shared. At 4 cols/thread the
// per-warp LDC demand (324 x 8cyc) sits well under the fma-pipe demand.
__constant__ ulonglong2 cW3v[324];   // W3: 36 rows x 9 ulonglong2
__constant__ float      cW4f[36];
__constant__ float      cb3f[36], cb4f[1];

static __device__ __forceinline__ u64 pack2(float lo, float hi) {
    u64 r; asm("mov.b64 %0,{%1,%2};" : "=l"(r) : "f"(lo), "f"(hi)); return r;
}
static __device__ __forceinline__ void unpack2(u64 v, float& lo, float& hi) {
    asm("mov.b64 {%0,%1},%2;" : "=f"(lo), "=f"(hi) : "l"(v));
}
static __device__ __forceinline__ u64 fma2(u64 a, u64 b, u64 c) {
    u64 d; asm("fma.rn.f32x2 %0,%1,%2,%3;" : "=l"(d) : "l"(a), "l"(b), "l"(c)); return d;
}
// horizontal add of the two f32 lanes (bias pre-folded into lane 0)
static __device__ __forceinline__ float hadd(u64 v) {
    float lo, hi; unpack2(v, lo, hi);
    return lo + hi;
}
// float atomic max via sign-split integer atomics (no return -> REDG)
static __device__ __forceinline__ void atomicMaxF(float* a, float v) {
    if (v >= 0.0f) atomicMax((int*)a, __float_as_int(v));
    else           atomicMin((unsigned int*)a, __float_as_uint(v));
}

__global__ void init_out_kernel(float* out, int n) {
    int i = blockIdx.x * blockDim.x + threadIdx.x;
    if (i < n) out[i] = (i < NCOLS) ? SENT : 1.0f;   // trailing element(s) = flag
}

// Layers 1+2 for ONE column pair (2 cols packed in f32x2 lanes), h1 local.
static __device__ __forceinline__ void layers12(
    const ulonglong2* sW1, const u64* sb1,
    const ulonglong2* sW2, const u64* sW2t, const u64* sb2,
    u64 xv00, u64 xv01, u64 xv10, u64 xv11,
    u64 (&h2)[2][18])
{
    u64 h1[2][9];
    #pragma unroll
    for (int j = 0; j < 18; j += 2) {
        float ho[2][2];
        #pragma unroll
        for (int s = 0; s < 2; s++) {
            const int jj = j + s;
            ulonglong2 w = sW1[jj];
            u64 bb = sb1[jj];
            u64 a0 = fma2(w.x, xv00, bb);
            u64 a1 = fma2(w.x, xv10, bb);
            a0 = fma2(w.y, xv01, a0);
            a1 = fma2(w.y, xv11, a1);
            ho[s][0] = fmaxf(hadd(a0), 0.0f);
            ho[s][1] = fmaxf(hadd(a1), 0.0f);
        }
        h1[0][j / 2] = pack2(ho[0][0], ho[1][0]);
        h1[1][j / 2] = pack2(ho[0][1], ho[1][1]);
    }

    #pragma unroll 4
    for (int j = 0; j < 36; j += 2) {
        float ho[2][2];
        #pragma unroll
        for (int s = 0; s < 2; s++) {
            const int jj = j + s;
            u64 a0 = sb2[jj], a1 = sb2[jj];
            #pragma unroll
            for (int q = 0; q < 4; q++) {
                ulonglong2 w = sW2[jj * 4 + q];
                a0 = fma2(w.x, h1[0][2 * q], a0);
                a1 = fma2(w.x, h1[1][2 * q], a1);
                a0 = fma2(w.y, h1[0][2 * q + 1], a0);
                a1 = fma2(w.y, h1[1][2 * q + 1], a1);
            }
            u64 wt = sW2t[jj];
            a0 = fma2(wt, h1[0][8], a0);
            a1 = fma2(wt, h1[1][8], a1);
            ho[s][0] = fmaxf(hadd(a0), 0.0f);
            ho[s][1] = fmaxf(hadd(a1), 0.0f);
        }
        h2[0][j / 2] = pack2(ho[0][0], ho[1][0]);
        h2[1][j / 2] = pack2(ho[0][1], ho[1][1]);
    }
}

__global__ __launch_bounds__(128) void mlp_scatter_kernel(
    const float* __restrict__ x,        // (4, K) row-major
    const int* __restrict__ tix,        // (K, 2) int32, col index at [2k+1]
    const float* __restrict__ W1, const float* __restrict__ b1,
    const float* __restrict__ W2, const float* __restrict__ b2,
    float* __restrict__ out)
{
    __shared__ ulonglong2 sW1[18];      // W1: 18 rows x 4 w
    __shared__ ulonglong2 sW2[144];     // W2: 36 rows x (4 x ulonglong2)
    __shared__ u64        sW2t[36];     // W2 row tails
    __shared__ u64 sb1[18], sb2[36];

    const int t = threadIdx.x;
    for (int i = t; i < 18;  i += 128) sW1[i] = ((const ulonglong2*)W1)[i];
    for (int i = t; i < 18;  i += 128) sb1[i] = pack2(b1[i], 0.0f);
    for (int i = t; i < 144; i += 128) {
        int row = i >> 2, q = i & 3;
        sW2[i] = make_ulonglong2(((const u64*)W2)[row * 9 + 2 * q],
                                 ((const u64*)W2)[row * 9 + 2 * q + 1]);
    }
    for (int i = t; i < 36;  i += 128) sW2t[i] = ((const u64*)W2)[i * 9 + 8];
    for (int i = t; i < 36;  i += 128) sb2[i] = pack2(b2[i], 0.0f);
    __syncthreads();

    const unsigned k0 = 4u * (blockIdx.x * 128u + (unsigned)t);
    if (k0 >= KTOT) return;

    // 4 columns: pair A = cols k0,k0+1 ; pair B = cols k0+2,k0+3.
    float4 r0 = *reinterpret_cast<const float4*>(x + 0 * (size_t)KTOT + k0);
    float4 r1 = *reinterpret_cast<const float4*>(x + 1 * (size_t)KTOT + k0);
    float4 r2 = *reinterpret_cast<const float4*>(x + 2 * (size_t)KTOT + k0);
    float4 r3 = *reinterpret_cast<const float4*>(x + 3 * (size_t)KTOT + k0);

    // Pass A: layers 1+2 for cols k0,k0+1
    u64 h2A[2][18];
    layers12(sW1, sb1, sW2, sW2t, sb2,
             pack2(r0.x, r1.x), pack2(r2.x, r3.x),
             pack2(r0.y, r1.y), pack2(r2.y, r3.y), h2A);

    // Pass B: layers 1+2 for cols k0+2,k0+3
    u64 h2B[2][18];
    layers12(sW1, sb1, sW2, sW2t, sb2,
             pack2(r0.z, r1.z), pack2(r2.z, r3.z),
             pack2(r0.w, r1.w), pack2(r2.w, r3.w), h2B);

    // ---- Layers 3+4 fused (constant-port weights): 36 -> 36 -> 1 ----
    // One row per iteration; 4 accumulator chains (4 columns). Each constant
    // weight load feeds 4 FFMA2.
    float v0 = cb4f[0], v1 = v0, v2 = v0, v3 = v0;
    #pragma unroll 4
    for (int j = 0; j < 36; j++) {
        u64 bb = pack2(cb3f[j], 0.0f);
        u64 a0 = bb, a1 = bb, a2 = bb, a3 = bb;
        #pragma unroll
        for (int q = 0; q < 9; q++) {
            ulonglong2 w = cW3v[j * 9 + q];
            a0 = fma2(w.x, h2A[0][2 * q], a0);
            a1 = fma2(w.x, h2A[1][2 * q], a1);
            a2 = fma2(w.x, h2B[0][2 * q], a2);
            a3 = fma2(w.x, h2B[1][2 * q], a3);
            a0 = fma2(w.y, h2A[0][2 * q + 1], a0);
            a1 = fma2(w.y, h2A[1][2 * q + 1], a1);
            a2 = fma2(w.y, h2B[0][2 * q + 1], a2);
            a3 = fma2(w.y, h2B[1][2 * q + 1], a3);
        }
        float w4 = cW4f[j];
        v0 = fmaf(w4, fmaxf(hadd(a0), 0.0f), v0);
        v1 = fmaf(w4, fmaxf(hadd(a1), 0.0f), v1);
        v2 = fmaf(w4, fmaxf(hadd(a2), 0.0f), v2);
        v3 = fmaf(w4, fmaxf(hadd(a3), 0.0f), v3);
    }

    // (K,2) int32 pairs: column index at odd positions
    const int4 p01 = *reinterpret_cast<const int4*>(tix + 2 * (size_t)k0);
    const int4 p23 = *reinterpret_cast<const int4*>(tix + 2 * (size_t)k0 + 4);
    if ((unsigned)p01.y < NCOLS) atomicMaxF(out + p01.y, v0);
    if ((unsigned)p01.w < NCOLS) atomicMaxF(out + p01.w, v1);
    if ((unsigned)p23.y < NCOLS) atomicMaxF(out + p23.y, v2);
    if ((unsigned)p23.w < NCOLS) atomicMaxF(out + p23.w, v3);
}

extern "C" void kernel_launch(void* const* d_in, const int* in_sizes, int n_in,
                              void* d_out, int out_size) {
    const float* x   = (const float*)d_in[0];
    const int*   tix = (const int*)d_in[1];
    const float* W1 = (const float*)d_in[2];
    const float* b1 = (const float*)d_in[3];
    const float* W2 = (const float*)d_in[4];
    const float* b2 = (const float*)d_in[5];
    float* out = (float*)d_out;

    // Stage the big layer into constant memory (async D2D memcpy nodes).
    cudaMemcpyToSymbolAsync(cW3v, d_in[6], 1296 * 4, 0, cudaMemcpyDeviceToDevice);
    cudaMemcpyToSymbolAsync(cb3f, d_in[7],   36 * 4, 0, cudaMemcpyDeviceToDevice);
    cudaMemcpyToSymbolAsync(cW4f, d_in[8],   36 * 4, 0, cudaMemcpyDeviceToDevice);
    cudaMemcpyToSymbolAsync(cb4f, d_in[9],    1 * 4, 0, cudaMemcpyDeviceToDevice);

    init_out_kernel<<<(out_size + 255) / 256, 256>>>(out, out_size);

    const int nthreads = KTOT / 4;                 // 4 columns per thread
    mlp_scatter_kernel<<<(nthreads + 127) / 128, 128>>>(
        x, tix, W1, b1, W2, b2, out);
}